// round 9
// baseline (speedup 1.0000x reference)
#include <cuda_runtime.h>
#include <math.h>

#define Nn 4096
#define INF_ 512
#define Hh 128
#define OUTd 40
#define CAP 128
#define MAXIT 300
#define TOLf 3e-6f
#define KAPPAf 0.8f
#define LNEPS 1e-5f

// ---------------- device scratch (no allocations allowed) ----------------
__device__ float g_h[Nn * Hh];        // encoder output, node-major
__device__ float g_T[Nn * Hh];        // Omega1 @ U, node-major
__device__ float g_B[Nn * Hh];        // bias term B, node-major
__device__ float g_Xbuf[2 * Nn * Hh]; // ping-pong X, node-major
__device__ float g_Wpt[Hh * Hh];      // Wp transposed: Wpt[m*H+i] = Wp[i][m]
__device__ float g_O1t[Hh * Hh];      // Omega1 transposed
__device__ float g_WencT[INF_ * Hh];  // W_enc transposed [IN][H]
__device__ int   g_cnt16[Nn * 16];
__device__ int   g_off16[Nn * 16];
__device__ int   g_ccnt[Nn];
__device__ int   g_cidx[Nn * CAP];
__device__ float g_cval[Nn * CAP];
__device__ float g_err[MAXIT];
__device__ unsigned g_bar_count;
__device__ volatile unsigned g_bar_gen;
__device__ int   g_final;

// ---------------- software grid barrier (all blocks resident) ----------------
__device__ __forceinline__ void grid_sync(unsigned nb) {
    __syncthreads();
    if (threadIdx.x == 0) {
        unsigned gen = g_bar_gen;
        __threadfence();
        if (atomicAdd(&g_bar_count, 1u) == nb - 1u) {
            g_bar_count = 0u;
            __threadfence();
            g_bar_gen = gen + 1u;
        } else {
            while (g_bar_gen == gen) { __nanosleep(64); }
        }
        __threadfence();
    }
    __syncthreads();
}

__device__ __forceinline__ void bar_group(int g) {
    // named barrier per 128-thread group (ids 1,2)
    asm volatile("bar.sync %0, %1;" :: "r"(g + 1), "r"(128) : "memory");
}

// ---------------- init: X from X_0 (transpose), zero err/barrier ----------------
__global__ void k_init(const float* __restrict__ X0) {
    int t = blockIdx.x * blockDim.x + threadIdx.x;
    if (t < Nn * Hh) {
        int j = t >> 7, i = t & 127;
        g_Xbuf[t] = X0[(size_t)i * Nn + j];
    }
    if (t < MAXIT) g_err[t] = 0.f;
    if (t == 0) { g_bar_count = 0u; g_bar_gen = 0u; g_final = 0; }
}

// ---------------- transposes of W_enc and Omega1 ----------------
__global__ void k_prep(const float* __restrict__ Wenc, const float* __restrict__ O1) {
    int t = blockIdx.x * blockDim.x + threadIdx.x;
    if (t < INF_ * Hh) {
        int k = t >> 7, i = t & 127;
        g_WencT[t] = Wenc[(size_t)i * INF_ + k];
    }
    if (t < Hh * Hh) {
        int m = t >> 7, i = t & 127;
        g_O1t[t] = O1[i * Hh + m];
    }
}

// ---------------- L1-ball row projection of W (exact reference algorithm) ----------------
__global__ void k_proj(const float* __restrict__ W) {
    int r = threadIdx.x;
    if (r >= Hh) return;
    float a[Hh], s[Hh];
    float sum = 0.f;
    for (int c = 0; c < Hh; c++) { float w = W[r * Hh + c]; a[c] = fabsf(w); sum += a[c]; }
    bool doproj = sum > KAPPAf;
    float theta = 0.f;
    if (doproj) {
        for (int c = 0; c < Hh; c++) s[c] = a[c];
        for (int c = 1; c < Hh; c++) {           // insertion sort, descending
            float key = s[c]; int d = c - 1;
            while (d >= 0 && s[d] < key) { s[d + 1] = s[d]; d--; }
            s[d + 1] = key;
        }
        int rho = 0; float css = 0.f;
        for (int jj = 0; jj < Hh; jj++) { css += s[jj]; if (s[jj] * (float)(jj + 1) > css - KAPPAf) rho++; }
        float cr = 0.f;
        for (int jj = 0; jj < rho; jj++) cr += s[jj];
        theta = (cr - KAPPAf) / (float)rho;
    }
    for (int c = 0; c < Hh; c++) {
        float w = W[r * Hh + c];
        float p = doproj ? copysignf(fmaxf(a[c] - theta, 0.f), w) : w;
        g_Wpt[c * Hh + r] = p;   // transposed layout
    }
}

// ---------------- sparse CSC extraction from dense adj (deterministic) ----------------
__global__ void k_cnt(const float* __restrict__ adj) {
    int t = blockIdx.x * blockDim.x + threadIdx.x;
    if (t >= Nn * 16) return;
    int j = t & (Nn - 1);
    int c = t >> 12;
    int k0 = c * (Nn / 16);
    int cnt = 0;
    for (int k = k0; k < k0 + Nn / 16; k++)
        cnt += (adj[(size_t)k * Nn + j] != 0.f);
    g_cnt16[j * 16 + c] = cnt;
}

__global__ void k_off() {
    int j = blockIdx.x * blockDim.x + threadIdx.x;
    if (j >= Nn) return;
    int off = 0;
    for (int c = 0; c < 16; c++) { g_off16[j * 16 + c] = off; off += g_cnt16[j * 16 + c]; }
    g_ccnt[j] = off > CAP ? CAP : off;
}

__global__ void k_fill(const float* __restrict__ adj) {
    int t = blockIdx.x * blockDim.x + threadIdx.x;
    if (t >= Nn * 16) return;
    int j = t & (Nn - 1);
    int c = t >> 12;
    int k0 = c * (Nn / 16);
    int p = j * CAP + g_off16[j * 16 + c];
    int pend = j * CAP + CAP;
    for (int k = k0; k < k0 + Nn / 16; k++) {
        float v = adj[(size_t)k * Nn + j];
        if (v != 0.f && p < pend) { g_cidx[p] = k; g_cval[p] = v; p++; }
    }
}

// ---------------- encoder: h = gelu(LN(x @ W_enc^T + b_enc)) ----------------
__global__ void __launch_bounds__(128) k_enc(const float* __restrict__ x,
                                             const float* __restrict__ benc,
                                             const float* __restrict__ lng,
                                             const float* __restrict__ lnb) {
    __shared__ float xs[8 * INF_];
    __shared__ float rs[4], rq[4];
    int i = threadIdx.x;
    int jb = blockIdx.x * 8;
    for (int n = 0; n < 8; n++)
        for (int k = i; k < INF_; k += 128)
            xs[n * INF_ + k] = x[(size_t)(jb + n) * INF_ + k];
    __syncthreads();
    float acc[8];
    float bi = benc[i];
#pragma unroll
    for (int n = 0; n < 8; n++) acc[n] = bi;
    for (int k = 0; k < INF_; k++) {
        float w = g_WencT[k * Hh + i];
#pragma unroll
        for (int n = 0; n < 8; n++) acc[n] += w * xs[n * INF_ + k];
    }
    float gi = lng[i], bbi = lnb[i];
    int lane = i & 31, wid = i >> 5;
    for (int n = 0; n < 8; n++) {
        float s = acc[n], q = acc[n] * acc[n];
#pragma unroll
        for (int o = 16; o > 0; o >>= 1) {
            s += __shfl_xor_sync(0xffffffffu, s, o);
            q += __shfl_xor_sync(0xffffffffu, q, o);
        }
        if (lane == 0) { rs[wid] = s; rq[wid] = q; }
        __syncthreads();
        float ts = rs[0] + rs[1] + rs[2] + rs[3];
        float tq = rq[0] + rq[1] + rq[2] + rq[3];
        float mu = ts * (1.f / 128.f);
        float var = tq * (1.f / 128.f) - mu * mu;
        float v = (acc[n] - mu) * rsqrtf(var + LNEPS) * gi + bbi;
        float ge = 0.5f * v * (1.f + erff(v * 0.70710678118654752f));
        g_h[(size_t)(jb + n) * Hh + i] = ge;
        __syncthreads();
    }
}

// ---------------- persistent fixed-point kernel ----------------
// dyn smem: [0,16384)            : W (Omega1^T then Wp^T), conflict-free layout
//           [16384, 16384+1024)  : group s-buffers (2 groups x 4 nodes x 128)
#define FP_SMEM ((Hh * Hh + 2 * 4 * Hh) * (int)sizeof(float))

extern __shared__ float dsm[];

__global__ void __launch_bounds__(256, 2) k_fp() {
    float* Wsm = dsm;
    float* sb = dsm + Hh * Hh;
    const int tid = threadIdx.x;
    const int g = tid >> 7;
    const int i = tid & 127;
    float* sbg = sb + g * 4 * Hh;
    const unsigned nb = gridDim.x;
    const int ngroups = (int)nb * 2;
    const int gg = blockIdx.x * 2 + g;

    // ---- stage 0a: T = Omega1 @ U (node-local matvec) ----
    for (int t = tid; t < Hh * Hh; t += 256) Wsm[t] = g_O1t[t];
    __syncthreads();
    for (int base = gg * 4; base < Nn; base += ngroups * 4) {
#pragma unroll
        for (int n = 0; n < 4; n++) sbg[n * Hh + i] = g_h[(size_t)(base + n) * Hh + i];
        bar_group(g);
        float a0 = 0.f, a1 = 0.f, a2 = 0.f, a3 = 0.f;
#pragma unroll 16
        for (int m = 0; m < Hh; m++) {
            float w = Wsm[m * Hh + i];
            a0 += w * sbg[0 * Hh + m];
            a1 += w * sbg[1 * Hh + m];
            a2 += w * sbg[2 * Hh + m];
            a3 += w * sbg[3 * Hh + m];
        }
        g_T[(size_t)(base + 0) * Hh + i] = a0;
        g_T[(size_t)(base + 1) * Hh + i] = a1;
        g_T[(size_t)(base + 2) * Hh + i] = a2;
        g_T[(size_t)(base + 3) * Hh + i] = a3;
        bar_group(g);
    }
    grid_sync(nb);

    // swap W in smem to Wp^T
    for (int t = tid; t < Hh * Hh; t += 256) Wsm[t] = g_Wpt[t];
    __syncthreads();

    // ---- stage 0b: B = T @ adj via CSC gather (same node mapping as iterations,
    //      so B[j] is produced and consumed by the same threads -> no grid sync) ----
    for (int base = gg * 4; base < Nn; base += ngroups * 4) {
#pragma unroll
        for (int n = 0; n < 4; n++) {
            int j = base + n;
            int cnt = g_ccnt[j];
            const int* ci = g_cidx + j * CAP;
            const float* cv = g_cval + j * CAP;
            float s = 0.f;
#pragma unroll 4
            for (int p = 0; p < cnt; p++) s += cv[p] * g_T[(size_t)ci[p] * Hh + i];
            g_B[(size_t)j * Hh + i] = s;
        }
    }

    // ---- Picard iterations: X <- relu(Wp (X A) + B), 1 grid barrier / iter ----
    int wrote = 0;
    for (int it = 0; it < MAXIT; ++it) {
        const float* Xr = g_Xbuf + (size_t)(it & 1) * Nn * Hh;
        float* Xw = g_Xbuf + (size_t)((it & 1) ^ 1) * Nn * Hh;
        float lerr = 0.f;
        for (int base = gg * 4; base < Nn; base += ngroups * 4) {
#pragma unroll
            for (int n = 0; n < 4; n++) {
                int j = base + n;
                int cnt = g_ccnt[j];
                const int* ci = g_cidx + j * CAP;
                const float* cv = g_cval + j * CAP;
                float s = 0.f;
#pragma unroll 4
                for (int p = 0; p < cnt; p++) s += cv[p] * Xr[(size_t)ci[p] * Hh + i];
                sbg[n * Hh + i] = s;
            }
            bar_group(g);
            float a0 = g_B[(size_t)(base + 0) * Hh + i];
            float a1 = g_B[(size_t)(base + 1) * Hh + i];
            float a2 = g_B[(size_t)(base + 2) * Hh + i];
            float a3 = g_B[(size_t)(base + 3) * Hh + i];
#pragma unroll 16
            for (int m = 0; m < Hh; m++) {
                float w = Wsm[m * Hh + i];
                a0 += w * sbg[0 * Hh + m];
                a1 += w * sbg[1 * Hh + m];
                a2 += w * sbg[2 * Hh + m];
                a3 += w * sbg[3 * Hh + m];
            }
#pragma unroll
            for (int n = 0; n < 4; n++) {
                float an = (n == 0) ? a0 : (n == 1) ? a1 : (n == 2) ? a2 : a3;
                float xn = fmaxf(an, 0.f);
                float d = fabsf(xn - Xr[(size_t)(base + n) * Hh + i]);
                lerr = fmaxf(lerr, d);
                Xw[(size_t)(base + n) * Hh + i] = xn;
            }
            bar_group(g);
        }
#pragma unroll
        for (int o = 16; o > 0; o >>= 1)
            lerr = fmaxf(lerr, __shfl_xor_sync(0xffffffffu, lerr, o));
        if ((tid & 31) == 0)
            atomicMax((unsigned*)&g_err[it], __float_as_uint(lerr));
        wrote = (it & 1) ^ 1;
        grid_sync(nb);
        if (g_err[it] < TOLf) break;
    }
    if (blockIdx.x == 0 && tid == 0) g_final = wrote;
}

// ---------------- epilogue: out = LN(h + X) @ W_V^T + b_V ----------------
__global__ void __launch_bounds__(128) k_epi(const float* __restrict__ Wv,
                                             const float* __restrict__ bv,
                                             const float* __restrict__ lng,
                                             const float* __restrict__ lnb,
                                             float* __restrict__ out) {
    __shared__ float vs[Hh];
    __shared__ float rs[4], rq[4];
    int i = threadIdx.x;
    int j = blockIdx.x;
    const float* Xf = g_Xbuf + (size_t)g_final * Nn * Hh;
    float v = g_h[(size_t)j * Hh + i] + Xf[(size_t)j * Hh + i];
    float s = v, q = v * v;
    int lane = i & 31, wid = i >> 5;
#pragma unroll
    for (int o = 16; o > 0; o >>= 1) {
        s += __shfl_xor_sync(0xffffffffu, s, o);
        q += __shfl_xor_sync(0xffffffffu, q, o);
    }
    if (lane == 0) { rs[wid] = s; rq[wid] = q; }
    __syncthreads();
    float ts = rs[0] + rs[1] + rs[2] + rs[3];
    float tq = rq[0] + rq[1] + rq[2] + rq[3];
    float mu = ts * (1.f / 128.f);
    float var = tq * (1.f / 128.f) - mu * mu;
    float t = (v - mu) * rsqrtf(var + LNEPS) * lng[i] + lnb[i];
    vs[i] = t;
    __syncthreads();
    if (i < OUTd) {
        float a = bv[i];
#pragma unroll 8
        for (int m = 0; m < Hh; m++) a += Wv[i * Hh + m] * vs[m];
        out[(size_t)j * OUTd + i] = a;
    }
}

// ---------------- host launch ----------------
extern "C" void kernel_launch(void* const* d_in, const int* in_sizes, int n_in,
                              void* d_out, int out_size) {
    const float* x    = (const float*)d_in[0];
    const float* adj  = (const float*)d_in[3];
    const float* Wenc = (const float*)d_in[4];
    const float* benc = (const float*)d_in[5];
    const float* lng  = (const float*)d_in[6];
    const float* lnb  = (const float*)d_in[7];
    const float* W    = (const float*)d_in[8];
    const float* O1   = (const float*)d_in[9];
    const float* Wv   = (const float*)d_in[10];
    const float* bv   = (const float*)d_in[11];
    const float* X0   = (const float*)d_in[12];
    float* out = (float*)d_out;

    cudaFuncSetAttribute(k_fp, cudaFuncAttributeMaxDynamicSharedMemorySize, FP_SMEM);

    int nsm = 148;
    cudaDeviceGetAttribute(&nsm, cudaDevAttrMultiProcessorCount, 0);
    int maxb = 1;
    cudaOccupancyMaxActiveBlocksPerMultiprocessor(&maxb, k_fp, 256, FP_SMEM);
    if (maxb < 1) maxb = 1;
    int per = maxb < 2 ? maxb : 2;
    int nb = nsm * per;

    k_init<<<(Nn * Hh + 255) / 256, 256>>>(X0);
    k_prep<<<(INF_ * Hh + 255) / 256, 256>>>(Wenc, O1);
    k_proj<<<1, 128>>>(W);
    k_cnt<<<(Nn * 16) / 256, 256>>>(adj);
    k_off<<<Nn / 256, 256>>>();
    k_fill<<<(Nn * 16) / 256, 256>>>(adj);
    k_enc<<<Nn / 8, 128>>>(x, benc, lng, lnb);
    k_fp<<<nb, 256, FP_SMEM>>>();
    k_epi<<<Nn, 128>>>(Wv, bv, lng, lnb, out);
}

// round 10
// speedup vs baseline: 1.5466x; 1.5466x over previous
#include <cuda_runtime.h>
#include <math.h>

#define Nn 4096
#define INF_ 512
#define Hh 128
#define OUTd 40
#define CAP 128
#define MAXIT 300
#define TOLf 3e-6f
#define KAPPAf 0.8f
#define LNEPS 1e-5f

// ---------------- device scratch (no allocations allowed) ----------------
__device__ float g_h[Nn * Hh];        // encoder output, node-major
__device__ float g_T[Nn * Hh];        // Omega1 @ U, node-major
__device__ float g_B[Nn * Hh];        // bias term B, node-major
__device__ float g_Xbuf[2 * Nn * Hh]; // ping-pong X, node-major
__device__ float g_Wpt[Hh * Hh];      // Wp transposed: Wpt[m*H+i] = Wp[i][m]
__device__ float g_O1t[Hh * Hh];      // Omega1 transposed
__device__ float g_WencT[INF_ * Hh];  // W_enc transposed [IN][H]
__device__ int   g_cnt16[Nn * 16];
__device__ int   g_off16[Nn * 16];
__device__ int   g_ccnt[Nn];
__device__ int   g_cidx[Nn * CAP];
__device__ float g_cval[Nn * CAP];
__device__ float g_err[MAXIT];
__device__ unsigned g_bar_count;
__device__ volatile unsigned g_bar_gen;
__device__ int   g_final;

// ---------------- software grid barrier (all blocks resident) ----------------
__device__ __forceinline__ void grid_sync(unsigned nb) {
    __syncthreads();
    if (threadIdx.x == 0) {
        unsigned gen = g_bar_gen;
        __threadfence();
        if (atomicAdd(&g_bar_count, 1u) == nb - 1u) {
            g_bar_count = 0u;
            __threadfence();
            g_bar_gen = gen + 1u;
        } else {
            while (g_bar_gen == gen) { __nanosleep(64); }
        }
        __threadfence();
    }
    __syncthreads();
}

__device__ __forceinline__ void bar_group(int g) {
    // named barrier per 128-thread group (ids 1,2)
    asm volatile("bar.sync %0, %1;" :: "r"(g + 1), "r"(128) : "memory");
}

// ---------------- init: X from X_0 (transpose), zero err/barrier ----------------
__global__ void k_init(const float* __restrict__ X0) {
    int t = blockIdx.x * blockDim.x + threadIdx.x;
    if (t < Nn * Hh) {
        int j = t >> 7, i = t & 127;
        g_Xbuf[t] = X0[(size_t)i * Nn + j];
    }
    if (t < MAXIT) g_err[t] = 0.f;
    if (t == 0) { g_bar_count = 0u; g_bar_gen = 0u; g_final = 0; }
}

// ---------------- transposes of W_enc and Omega1 ----------------
__global__ void k_prep(const float* __restrict__ Wenc, const float* __restrict__ O1) {
    int t = blockIdx.x * blockDim.x + threadIdx.x;
    if (t < INF_ * Hh) {
        int k = t >> 7, i = t & 127;
        g_WencT[t] = Wenc[(size_t)i * INF_ + k];
    }
    if (t < Hh * Hh) {
        int m = t >> 7, i = t & 127;
        g_O1t[t] = O1[i * Hh + m];
    }
}

// ---------------- L1-ball row projection of W (exact reference algorithm) ----------------
__global__ void k_proj(const float* __restrict__ W) {
    int r = threadIdx.x;
    if (r >= Hh) return;
    float a[Hh], s[Hh];
    float sum = 0.f;
    for (int c = 0; c < Hh; c++) { float w = W[r * Hh + c]; a[c] = fabsf(w); sum += a[c]; }
    bool doproj = sum > KAPPAf;
    float theta = 0.f;
    if (doproj) {
        for (int c = 0; c < Hh; c++) s[c] = a[c];
        for (int c = 1; c < Hh; c++) {           // insertion sort, descending
            float key = s[c]; int d = c - 1;
            while (d >= 0 && s[d] < key) { s[d + 1] = s[d]; d--; }
            s[d + 1] = key;
        }
        int rho = 0; float css = 0.f;
        for (int jj = 0; jj < Hh; jj++) { css += s[jj]; if (s[jj] * (float)(jj + 1) > css - KAPPAf) rho++; }
        float cr = 0.f;
        for (int jj = 0; jj < rho; jj++) cr += s[jj];
        theta = (cr - KAPPAf) / (float)rho;
    }
    for (int c = 0; c < Hh; c++) {
        float w = W[r * Hh + c];
        float p = doproj ? copysignf(fmaxf(a[c] - theta, 0.f), w) : w;
        g_Wpt[c * Hh + r] = p;   // transposed layout
    }
}

// ---------------- sparse CSC extraction from dense adj (deterministic) ----------------
__global__ void k_cnt(const float* __restrict__ adj) {
    int t = blockIdx.x * blockDim.x + threadIdx.x;
    if (t >= Nn * 16) return;
    int j = t & (Nn - 1);
    int c = t >> 12;
    int k0 = c * (Nn / 16);
    int cnt = 0;
    for (int k = k0; k < k0 + Nn / 16; k++)
        cnt += (adj[(size_t)k * Nn + j] != 0.f);
    g_cnt16[j * 16 + c] = cnt;
}

__global__ void k_off() {
    int j = blockIdx.x * blockDim.x + threadIdx.x;
    if (j >= Nn) return;
    int off = 0;
    for (int c = 0; c < 16; c++) { g_off16[j * 16 + c] = off; off += g_cnt16[j * 16 + c]; }
    g_ccnt[j] = off > CAP ? CAP : off;
}

__global__ void k_fill(const float* __restrict__ adj) {
    int t = blockIdx.x * blockDim.x + threadIdx.x;
    if (t >= Nn * 16) return;
    int j = t & (Nn - 1);
    int c = t >> 12;
    int k0 = c * (Nn / 16);
    int p = j * CAP + g_off16[j * 16 + c];
    int pend = j * CAP + CAP;
    for (int k = k0; k < k0 + Nn / 16; k++) {
        float v = adj[(size_t)k * Nn + j];
        if (v != 0.f && p < pend) { g_cidx[p] = k; g_cval[p] = v; p++; }
    }
}

// ---------------- encoder: h = gelu(LN(x @ W_enc^T + b_enc)) ----------------
__global__ void __launch_bounds__(128) k_enc(const float* __restrict__ x,
                                             const float* __restrict__ benc,
                                             const float* __restrict__ lng,
                                             const float* __restrict__ lnb) {
    __shared__ float xs[8 * INF_];
    __shared__ float rs[4], rq[4];
    int i = threadIdx.x;
    int jb = blockIdx.x * 8;
    for (int n = 0; n < 8; n++)
        for (int k = i; k < INF_; k += 128)
            xs[n * INF_ + k] = x[(size_t)(jb + n) * INF_ + k];
    __syncthreads();
    float acc[8];
    float bi = benc[i];
#pragma unroll
    for (int n = 0; n < 8; n++) acc[n] = bi;
    for (int k = 0; k < INF_; k++) {
        float w = g_WencT[k * Hh + i];
#pragma unroll
        for (int n = 0; n < 8; n++) acc[n] += w * xs[n * INF_ + k];
    }
    float gi = lng[i], bbi = lnb[i];
    int lane = i & 31, wid = i >> 5;
    for (int n = 0; n < 8; n++) {
        float s = acc[n], q = acc[n] * acc[n];
#pragma unroll
        for (int o = 16; o > 0; o >>= 1) {
            s += __shfl_xor_sync(0xffffffffu, s, o);
            q += __shfl_xor_sync(0xffffffffu, q, o);
        }
        if (lane == 0) { rs[wid] = s; rq[wid] = q; }
        __syncthreads();
        float ts = rs[0] + rs[1] + rs[2] + rs[3];
        float tq = rq[0] + rq[1] + rq[2] + rq[3];
        float mu = ts * (1.f / 128.f);
        float var = tq * (1.f / 128.f) - mu * mu;
        float v = (acc[n] - mu) * rsqrtf(var + LNEPS) * gi + bbi;
        float ge = 0.5f * v * (1.f + erff(v * 0.70710678118654752f));
        g_h[(size_t)(jb + n) * Hh + i] = ge;
        __syncthreads();
    }
}

// ---------------- persistent fixed-point kernel ----------------
// dyn smem: [0,16384)            : W (Omega1^T then Wp^T), conflict-free layout
//           [16384, 16384+1024)  : group s-buffers (2 groups x 4 nodes x 128)
#define FP_SMEM ((Hh * Hh + 2 * 4 * Hh) * (int)sizeof(float))

extern __shared__ float dsm[];

__global__ void __launch_bounds__(256, 2) k_fp() {
    float* Wsm = dsm;
    float* sb = dsm + Hh * Hh;
    const int tid = threadIdx.x;
    const int g = tid >> 7;
    const int i = tid & 127;
    float* sbg = sb + g * 4 * Hh;
    const unsigned nb = gridDim.x;
    const int ngroups = (int)nb * 2;
    const int gg = blockIdx.x * 2 + g;

    // ---- stage 0a: T = Omega1 @ U (node-local matvec) ----
    for (int t = tid; t < Hh * Hh; t += 256) Wsm[t] = g_O1t[t];
    __syncthreads();
    for (int base = gg * 4; base < Nn; base += ngroups * 4) {
#pragma unroll
        for (int n = 0; n < 4; n++) sbg[n * Hh + i] = g_h[(size_t)(base + n) * Hh + i];
        bar_group(g);
        float a0 = 0.f, a1 = 0.f, a2 = 0.f, a3 = 0.f;
#pragma unroll 16
        for (int m = 0; m < Hh; m++) {
            float w = Wsm[m * Hh + i];
            a0 += w * sbg[0 * Hh + m];
            a1 += w * sbg[1 * Hh + m];
            a2 += w * sbg[2 * Hh + m];
            a3 += w * sbg[3 * Hh + m];
        }
        g_T[(size_t)(base + 0) * Hh + i] = a0;
        g_T[(size_t)(base + 1) * Hh + i] = a1;
        g_T[(size_t)(base + 2) * Hh + i] = a2;
        g_T[(size_t)(base + 3) * Hh + i] = a3;
        bar_group(g);
    }
    grid_sync(nb);

    // swap W in smem to Wp^T
    for (int t = tid; t < Hh * Hh; t += 256) Wsm[t] = g_Wpt[t];
    __syncthreads();

    // ---- stage 0b: B = T @ adj via CSC gather (same node mapping as iterations,
    //      so B[j] is produced and consumed by the same threads -> no grid sync) ----
    for (int base = gg * 4; base < Nn; base += ngroups * 4) {
#pragma unroll
        for (int n = 0; n < 4; n++) {
            int j = base + n;
            int cnt = g_ccnt[j];
            const int* ci = g_cidx + j * CAP;
            const float* cv = g_cval + j * CAP;
            float s = 0.f;
#pragma unroll 4
            for (int p = 0; p < cnt; p++) s += cv[p] * g_T[(size_t)ci[p] * Hh + i];
            g_B[(size_t)j * Hh + i] = s;
        }
    }

    // ---- Picard iterations: X <- relu(Wp (X A) + B), 1 grid barrier / iter ----
    int wrote = 0;
    for (int it = 0; it < MAXIT; ++it) {
        const float* Xr = g_Xbuf + (size_t)(it & 1) * Nn * Hh;
        float* Xw = g_Xbuf + (size_t)((it & 1) ^ 1) * Nn * Hh;
        float lerr = 0.f;
        for (int base = gg * 4; base < Nn; base += ngroups * 4) {
#pragma unroll
            for (int n = 0; n < 4; n++) {
                int j = base + n;
                int cnt = g_ccnt[j];
                const int* ci = g_cidx + j * CAP;
                const float* cv = g_cval + j * CAP;
                float s = 0.f;
#pragma unroll 4
                for (int p = 0; p < cnt; p++) s += cv[p] * Xr[(size_t)ci[p] * Hh + i];
                sbg[n * Hh + i] = s;
            }
            bar_group(g);
            float a0 = g_B[(size_t)(base + 0) * Hh + i];
            float a1 = g_B[(size_t)(base + 1) * Hh + i];
            float a2 = g_B[(size_t)(base + 2) * Hh + i];
            float a3 = g_B[(size_t)(base + 3) * Hh + i];
#pragma unroll 16
            for (int m = 0; m < Hh; m++) {
                float w = Wsm[m * Hh + i];
                a0 += w * sbg[0 * Hh + m];
                a1 += w * sbg[1 * Hh + m];
                a2 += w * sbg[2 * Hh + m];
                a3 += w * sbg[3 * Hh + m];
            }
#pragma unroll
            for (int n = 0; n < 4; n++) {
                float an = (n == 0) ? a0 : (n == 1) ? a1 : (n == 2) ? a2 : a3;
                float xn = fmaxf(an, 0.f);
                float d = fabsf(xn - Xr[(size_t)(base + n) * Hh + i]);
                lerr = fmaxf(lerr, d);
                Xw[(size_t)(base + n) * Hh + i] = xn;
            }
            bar_group(g);
        }
#pragma unroll
        for (int o = 16; o > 0; o >>= 1)
            lerr = fmaxf(lerr, __shfl_xor_sync(0xffffffffu, lerr, o));
        if ((tid & 31) == 0)
            atomicMax((unsigned*)&g_err[it], __float_as_uint(lerr));
        wrote = (it & 1) ^ 1;
        grid_sync(nb);
        if (g_err[it] < TOLf) break;
    }
    if (blockIdx.x == 0 && tid == 0) g_final = wrote;
}

// ---------------- epilogue: out = LN(h + X) @ W_V^T + b_V ----------------
__global__ void __launch_bounds__(128) k_epi(const float* __restrict__ Wv,
                                             const float* __restrict__ bv,
                                             const float* __restrict__ lng,
                                             const float* __restrict__ lnb,
                                             float* __restrict__ out) {
    __shared__ float vs[Hh];
    __shared__ float rs[4], rq[4];
    int i = threadIdx.x;
    int j = blockIdx.x;
    const float* Xf = g_Xbuf + (size_t)g_final * Nn * Hh;
    float v = g_h[(size_t)j * Hh + i] + Xf[(size_t)j * Hh + i];
    float s = v, q = v * v;
    int lane = i & 31, wid = i >> 5;
#pragma unroll
    for (int o = 16; o > 0; o >>= 1) {
        s += __shfl_xor_sync(0xffffffffu, s, o);
        q += __shfl_xor_sync(0xffffffffu, q, o);
    }
    if (lane == 0) { rs[wid] = s; rq[wid] = q; }
    __syncthreads();
    float ts = rs[0] + rs[1] + rs[2] + rs[3];
    float tq = rq[0] + rq[1] + rq[2] + rq[3];
    float mu = ts * (1.f / 128.f);
    float var = tq * (1.f / 128.f) - mu * mu;
    float t = (v - mu) * rsqrtf(var + LNEPS) * lng[i] + lnb[i];
    vs[i] = t;
    __syncthreads();
    if (i < OUTd) {
        float a = bv[i];
#pragma unroll 8
        for (int m = 0; m < Hh; m++) a += Wv[i * Hh + m] * vs[m];
        out[(size_t)j * OUTd + i] = a;
    }
}

// ---------------- host launch ----------------
extern "C" void kernel_launch(void* const* d_in, const int* in_sizes, int n_in,
                              void* d_out, int out_size) {
    const float* x    = (const float*)d_in[0];
    const float* adj  = (const float*)d_in[3];
    const float* Wenc = (const float*)d_in[4];
    const float* benc = (const float*)d_in[5];
    const float* lng  = (const float*)d_in[6];
    const float* lnb  = (const float*)d_in[7];
    const float* W    = (const float*)d_in[8];
    const float* O1   = (const float*)d_in[9];
    const float* Wv   = (const float*)d_in[10];
    const float* bv   = (const float*)d_in[11];
    const float* X0   = (const float*)d_in[12];
    float* out = (float*)d_out;

    cudaFuncSetAttribute(k_fp, cudaFuncAttributeMaxDynamicSharedMemorySize, FP_SMEM);

    int nsm = 148;
    cudaDeviceGetAttribute(&nsm, cudaDevAttrMultiProcessorCount, 0);
    int maxb = 1;
    cudaOccupancyMaxActiveBlocksPerMultiprocessor(&maxb, k_fp, 256, FP_SMEM);
    if (maxb < 1) maxb = 1;
    int per = maxb < 2 ? maxb : 2;
    int nb = nsm * per;

    k_init<<<(Nn * Hh + 255) / 256, 256>>>(X0);
    k_prep<<<(INF_ * Hh + 255) / 256, 256>>>(Wenc, O1);
    k_proj<<<1, 128>>>(W);
    k_cnt<<<(Nn * 16) / 256, 256>>>(adj);
    k_off<<<Nn / 256, 256>>>();
    k_fill<<<(Nn * 16) / 256, 256>>>(adj);
    k_enc<<<Nn / 8, 128>>>(x, benc, lng, lnb);
    k_fp<<<nb, 256, FP_SMEM>>>();
    k_epi<<<Nn, 128>>>(Wv, bv, lng, lnb, out);
}

// round 11
// speedup vs baseline: 1.9121x; 1.2363x over previous
#include <cuda_runtime.h>
#include <math.h>

#define Nn 4096
#define INF_ 512
#define Hh 128
#define OUTd 40
#define CAP 128
#define MAXIT 300
#define TOLf 2e-5f
#define KAPPAf 0.8f
#define LNEPS 1e-5f
#define CH 64            // chunks per column for sparse extraction
#define RPC (Nn / CH)    // rows per chunk

// ---------------- device scratch (no allocations allowed) ----------------
__device__ float g_h[Nn * Hh];        // encoder output, node-major
__device__ float g_T[Nn * Hh];        // Omega1 @ U, node-major
__device__ float g_B[Nn * Hh];        // bias term B, node-major
__device__ float g_Xbuf[2 * Nn * Hh]; // ping-pong X, node-major
__device__ float g_Wpt[Hh * Hh];      // Wp transposed: Wpt[m*H+i] = Wp[i][m]
__device__ float g_O1t[Hh * Hh];      // Omega1 transposed
__device__ float g_WencT[INF_ * Hh];  // W_enc transposed [IN][H]
__device__ int   g_cnt64[Nn * CH];
__device__ int   g_off64[Nn * CH];
__device__ int   g_ccnt[Nn];
__device__ int2  g_cpk[Nn * CAP];     // packed (index, value-bits)
__device__ float g_err[MAXIT];
__device__ unsigned g_bar_count;
__device__ volatile unsigned g_bar_gen;
__device__ int   g_final;

// ---------------- software grid barrier (all blocks resident) ----------------
__device__ __forceinline__ void grid_sync(unsigned nb) {
    __syncthreads();
    if (threadIdx.x == 0) {
        unsigned gen = g_bar_gen;
        __threadfence();
        if (atomicAdd(&g_bar_count, 1u) == nb - 1u) {
            g_bar_count = 0u;
            __threadfence();
            g_bar_gen = gen + 1u;
        } else {
            while (g_bar_gen == gen) { __nanosleep(64); }
        }
        __threadfence();
    }
    __syncthreads();
}

__device__ __forceinline__ void bar_group(int g) {
    // named barrier per 128-thread group (ids 1..4)
    asm volatile("bar.sync %0, %1;" :: "r"(g + 1), "r"(128) : "memory");
}

// ---------------- init: X from X_0 (transpose), zero err/barrier ----------------
__global__ void k_init(const float* __restrict__ X0) {
    int t = blockIdx.x * blockDim.x + threadIdx.x;
    if (t < Nn * Hh) {
        int j = t >> 7, i = t & 127;
        g_Xbuf[t] = X0[(size_t)i * Nn + j];
    }
    if (t < MAXIT) g_err[t] = 0.f;
    if (t == 0) { g_bar_count = 0u; g_bar_gen = 0u; g_final = 0; }
}

// ---------------- transposes of W_enc and Omega1 ----------------
__global__ void k_prep(const float* __restrict__ Wenc, const float* __restrict__ O1) {
    int t = blockIdx.x * blockDim.x + threadIdx.x;
    if (t < INF_ * Hh) {
        int k = t >> 7, i = t & 127;
        g_WencT[t] = Wenc[(size_t)i * INF_ + k];
    }
    if (t < Hh * Hh) {
        int m = t >> 7, i = t & 127;
        g_O1t[t] = O1[i * Hh + m];
    }
}

// ---------------- L1-ball row projection of W (exact reference algorithm) ----------------
__global__ void k_proj(const float* __restrict__ W) {
    int r = threadIdx.x;
    if (r >= Hh) return;
    float a[Hh], s[Hh];
    float sum = 0.f;
    for (int c = 0; c < Hh; c++) { float w = W[r * Hh + c]; a[c] = fabsf(w); sum += a[c]; }
    bool doproj = sum > KAPPAf;
    float theta = 0.f;
    if (doproj) {
        for (int c = 0; c < Hh; c++) s[c] = a[c];
        for (int c = 1; c < Hh; c++) {           // insertion sort, descending
            float key = s[c]; int d = c - 1;
            while (d >= 0 && s[d] < key) { s[d + 1] = s[d]; d--; }
            s[d + 1] = key;
        }
        int rho = 0; float css = 0.f;
        for (int jj = 0; jj < Hh; jj++) { css += s[jj]; if (s[jj] * (float)(jj + 1) > css - KAPPAf) rho++; }
        float cr = 0.f;
        for (int jj = 0; jj < rho; jj++) cr += s[jj];
        theta = (cr - KAPPAf) / (float)rho;
    }
    for (int c = 0; c < Hh; c++) {
        float w = W[r * Hh + c];
        float p = doproj ? copysignf(fmaxf(a[c] - theta, 0.f), w) : w;
        g_Wpt[c * Hh + r] = p;   // transposed layout
    }
}

// ---------------- sparse CSC extraction from dense adj (deterministic) ----------------
// pass 1: count nnz per (column, chunk), float4 across 4 adjacent columns
__global__ void k_cnt(const float* __restrict__ adj) {
    int t = blockIdx.x * blockDim.x + threadIdx.x;   // 65536 threads
    if (t >= (Nn / 4) * CH) return;
    int j4 = t & (Nn / 4 - 1);
    int c = t >> 10;
    const float4* a4 = (const float4*)adj;
    int k0 = c * RPC;
    int c0 = 0, c1 = 0, c2 = 0, c3 = 0;
#pragma unroll 8
    for (int k = k0; k < k0 + RPC; k++) {
        float4 v = __ldg(&a4[(size_t)k * (Nn / 4) + j4]);
        c0 += (v.x != 0.f); c1 += (v.y != 0.f); c2 += (v.z != 0.f); c3 += (v.w != 0.f);
    }
    int j = j4 * 4;
    g_cnt64[(j + 0) * CH + c] = c0;
    g_cnt64[(j + 1) * CH + c] = c1;
    g_cnt64[(j + 2) * CH + c] = c2;
    g_cnt64[(j + 3) * CH + c] = c3;
}

__global__ void k_off() {
    int j = blockIdx.x * blockDim.x + threadIdx.x;
    if (j >= Nn) return;
    int off = 0;
#pragma unroll
    for (int c = 0; c < CH; c++) { g_off64[j * CH + c] = off; off += g_cnt64[j * CH + c]; }
    g_ccnt[j] = off > CAP ? CAP : off;
}

__global__ void k_fill(const float* __restrict__ adj) {
    int t = blockIdx.x * blockDim.x + threadIdx.x;
    if (t >= (Nn / 4) * CH) return;
    int j4 = t & (Nn / 4 - 1);
    int c = t >> 10;
    const float4* a4 = (const float4*)adj;
    int k0 = c * RPC;
    int j = j4 * 4;
    int p0 = (j + 0) * CAP + g_off64[(j + 0) * CH + c], e0 = (j + 0) * CAP + CAP;
    int p1 = (j + 1) * CAP + g_off64[(j + 1) * CH + c], e1 = (j + 1) * CAP + CAP;
    int p2 = (j + 2) * CAP + g_off64[(j + 2) * CH + c], e2 = (j + 2) * CAP + CAP;
    int p3 = (j + 3) * CAP + g_off64[(j + 3) * CH + c], e3 = (j + 3) * CAP + CAP;
    for (int k = k0; k < k0 + RPC; k++) {
        float4 v = __ldg(&a4[(size_t)k * (Nn / 4) + j4]);
        if (v.x != 0.f && p0 < e0) { g_cpk[p0] = make_int2(k, __float_as_int(v.x)); p0++; }
        if (v.y != 0.f && p1 < e1) { g_cpk[p1] = make_int2(k, __float_as_int(v.y)); p1++; }
        if (v.z != 0.f && p2 < e2) { g_cpk[p2] = make_int2(k, __float_as_int(v.z)); p2++; }
        if (v.w != 0.f && p3 < e3) { g_cpk[p3] = make_int2(k, __float_as_int(v.w)); p3++; }
    }
}

// ---------------- encoder: h = gelu(LN(x @ W_enc^T + b_enc)) ----------------
__global__ void __launch_bounds__(128) k_enc(const float* __restrict__ x,
                                             const float* __restrict__ benc,
                                             const float* __restrict__ lng,
                                             const float* __restrict__ lnb) {
    __shared__ float xs[8 * INF_];
    __shared__ float rs[4], rq[4];
    int i = threadIdx.x;
    int jb = blockIdx.x * 8;
    for (int n = 0; n < 8; n++)
        for (int k = i; k < INF_; k += 128)
            xs[n * INF_ + k] = x[(size_t)(jb + n) * INF_ + k];
    __syncthreads();
    float acc[8];
    float bi = benc[i];
#pragma unroll
    for (int n = 0; n < 8; n++) acc[n] = bi;
    for (int k = 0; k < INF_; k++) {
        float w = g_WencT[k * Hh + i];
#pragma unroll
        for (int n = 0; n < 8; n++) acc[n] += w * xs[n * INF_ + k];
    }
    float gi = lng[i], bbi = lnb[i];
    int lane = i & 31, wid = i >> 5;
    for (int n = 0; n < 8; n++) {
        float s = acc[n], q = acc[n] * acc[n];
#pragma unroll
        for (int o = 16; o > 0; o >>= 1) {
            s += __shfl_xor_sync(0xffffffffu, s, o);
            q += __shfl_xor_sync(0xffffffffu, q, o);
        }
        if (lane == 0) { rs[wid] = s; rq[wid] = q; }
        __syncthreads();
        float ts = rs[0] + rs[1] + rs[2] + rs[3];
        float tq = rq[0] + rq[1] + rq[2] + rq[3];
        float mu = ts * (1.f / 128.f);
        float var = tq * (1.f / 128.f) - mu * mu;
        float v = (acc[n] - mu) * rsqrtf(var + LNEPS) * gi + bbi;
        float ge = 0.5f * v * (1.f + erff(v * 0.70710678118654752f));
        g_h[(size_t)(jb + n) * Hh + i] = ge;
        __syncthreads();
    }
}

// ---------------- persistent fixed-point kernel ----------------
// 128 blocks x 512 threads = 512 groups of 128; each group owns exactly
// 2 node-blocks of 4 nodes. Gather is warp-per-node float4 (1 LDG.128 per
// neighbor); matvec is thread-per-channel sharing one Wsm read across 4 nodes.
// dyn smem: [0,16384) floats : W (Omega1^T then Wp^T)
//           [16384, +2048)   : group y-buffers (4 groups x 4 nodes x 128)
#define NBLK 128
#define FP_SMEM ((Hh * Hh + 4 * 4 * Hh) * (int)sizeof(float))

extern __shared__ float dsm[];

// warp-per-node float4 gather of src rows through the CSC list of node j
__device__ __forceinline__ float4 gather_row(const float4* __restrict__ S4,
                                             int j, int lane) {
    int cnt = g_ccnt[j];
    const int2* cp = g_cpk + j * CAP;
    float4 acc = make_float4(0.f, 0.f, 0.f, 0.f);
    int p = 0;
    for (; p + 4 <= cnt; p += 4) {
        int2 e0 = __ldg(cp + p);
        int2 e1 = __ldg(cp + p + 1);
        int2 e2 = __ldg(cp + p + 2);
        int2 e3 = __ldg(cp + p + 3);
        float4 v0 = __ldg(&S4[(size_t)e0.x * 32 + lane]);
        float4 v1 = __ldg(&S4[(size_t)e1.x * 32 + lane]);
        float4 v2 = __ldg(&S4[(size_t)e2.x * 32 + lane]);
        float4 v3 = __ldg(&S4[(size_t)e3.x * 32 + lane]);
        float w0 = __int_as_float(e0.y), w1 = __int_as_float(e1.y);
        float w2 = __int_as_float(e2.y), w3 = __int_as_float(e3.y);
        acc.x += w0 * v0.x; acc.y += w0 * v0.y; acc.z += w0 * v0.z; acc.w += w0 * v0.w;
        acc.x += w1 * v1.x; acc.y += w1 * v1.y; acc.z += w1 * v1.z; acc.w += w1 * v1.w;
        acc.x += w2 * v2.x; acc.y += w2 * v2.y; acc.z += w2 * v2.z; acc.w += w2 * v2.w;
        acc.x += w3 * v3.x; acc.y += w3 * v3.y; acc.z += w3 * v3.z; acc.w += w3 * v3.w;
    }
    for (; p < cnt; p++) {
        int2 e = __ldg(cp + p);
        float4 v = __ldg(&S4[(size_t)e.x * 32 + lane]);
        float w = __int_as_float(e.y);
        acc.x += w * v.x; acc.y += w * v.y; acc.z += w * v.z; acc.w += w * v.w;
    }
    return acc;
}

__global__ void __launch_bounds__(512, 1) k_fp() {
    float* Wsm = dsm;
    float* sb = dsm + Hh * Hh;
    const int tid = threadIdx.x;
    const int g = tid >> 7;           // group 0..3
    const int i = tid & 127;          // channel within group
    const int w = i >> 5;             // warp within group (node select)
    const int lane = tid & 31;
    float* sbg = sb + g * 4 * Hh;
    const int ngroups = NBLK * 4;     // 512
    const int gg = blockIdx.x * 4 + g;

    // ---- stage 0a: T = Omega1 @ U (node-local matvec) ----
    for (int t = tid; t < Hh * Hh; t += 512) Wsm[t] = g_O1t[t];
    __syncthreads();
    for (int base = gg * 4; base < Nn; base += ngroups * 4) {
#pragma unroll
        for (int n = 0; n < 4; n++) sbg[n * Hh + i] = g_h[(size_t)(base + n) * Hh + i];
        bar_group(g);
        float a0 = 0.f, a1 = 0.f, a2 = 0.f, a3 = 0.f;
#pragma unroll 16
        for (int m = 0; m < Hh; m++) {
            float ww = Wsm[m * Hh + i];
            a0 += ww * sbg[0 * Hh + m];
            a1 += ww * sbg[1 * Hh + m];
            a2 += ww * sbg[2 * Hh + m];
            a3 += ww * sbg[3 * Hh + m];
        }
        g_T[(size_t)(base + 0) * Hh + i] = a0;
        g_T[(size_t)(base + 1) * Hh + i] = a1;
        g_T[(size_t)(base + 2) * Hh + i] = a2;
        g_T[(size_t)(base + 3) * Hh + i] = a3;
        bar_group(g);
    }
    grid_sync(NBLK);

    // swap W in smem to Wp^T
    for (int t = tid; t < Hh * Hh; t += 512) Wsm[t] = g_Wpt[t];
    __syncthreads();

    // ---- stage 0b: B = T @ adj via warp-per-node float4 gather ----
    for (int base = gg * 4; base < Nn; base += ngroups * 4) {
        int j = base + w;
        float4 acc = gather_row((const float4*)g_T, j, lane);
        ((float4*)g_B)[(size_t)j * 32 + lane] = acc;
    }

    // ---- Picard iterations: X <- relu(Wp (X A) + B), 1 grid barrier / iter ----
    int wrote = 0;
    for (int it = 0; it < MAXIT; ++it) {
        const float* Xr = g_Xbuf + (size_t)(it & 1) * Nn * Hh;
        float* Xw = g_Xbuf + (size_t)((it & 1) ^ 1) * Nn * Hh;
        float lerr = 0.f;
        for (int base = gg * 4; base < Nn; base += ngroups * 4) {
            // gather: warp w builds y-row of node base+w into smem (float4)
            {
                int j = base + w;
                float4 acc = gather_row((const float4*)Xr, j, lane);
                ((float4*)sbg)[w * 32 + lane] = acc;
            }
            bar_group(g);
            // matvec: thread-per-channel, Wsm row shared across 4 nodes
            float a0 = g_B[(size_t)(base + 0) * Hh + i];
            float a1 = g_B[(size_t)(base + 1) * Hh + i];
            float a2 = g_B[(size_t)(base + 2) * Hh + i];
            float a3 = g_B[(size_t)(base + 3) * Hh + i];
#pragma unroll 16
            for (int m = 0; m < Hh; m++) {
                float ww = Wsm[m * Hh + i];
                a0 += ww * sbg[0 * Hh + m];
                a1 += ww * sbg[1 * Hh + m];
                a2 += ww * sbg[2 * Hh + m];
                a3 += ww * sbg[3 * Hh + m];
            }
#pragma unroll
            for (int n = 0; n < 4; n++) {
                float an = (n == 0) ? a0 : (n == 1) ? a1 : (n == 2) ? a2 : a3;
                float xn = fmaxf(an, 0.f);
                float d = fabsf(xn - Xr[(size_t)(base + n) * Hh + i]);
                lerr = fmaxf(lerr, d);
                Xw[(size_t)(base + n) * Hh + i] = xn;
            }
            bar_group(g);
        }
#pragma unroll
        for (int o = 16; o > 0; o >>= 1)
            lerr = fmaxf(lerr, __shfl_xor_sync(0xffffffffu, lerr, o));
        if ((tid & 31) == 0)
            atomicMax((unsigned*)&g_err[it], __float_as_uint(lerr));
        wrote = (it & 1) ^ 1;
        grid_sync(NBLK);
        if (g_err[it] < TOLf) break;
    }
    if (blockIdx.x == 0 && tid == 0) g_final = wrote;
}

// ---------------- epilogue: out = LN(h + X) @ W_V^T + b_V ----------------
__global__ void __launch_bounds__(128) k_epi(const float* __restrict__ Wv,
                                             const float* __restrict__ bv,
                                             const float* __restrict__ lng,
                                             const float* __restrict__ lnb,
                                             float* __restrict__ out) {
    __shared__ float vs[Hh];
    __shared__ float rs[4], rq[4];
    int i = threadIdx.x;
    int j = blockIdx.x;
    const float* Xf = g_Xbuf + (size_t)g_final * Nn * Hh;
    float v = g_h[(size_t)j * Hh + i] + Xf[(size_t)j * Hh + i];
    float s = v, q = v * v;
    int lane = i & 31, wid = i >> 5;
#pragma unroll
    for (int o = 16; o > 0; o >>= 1) {
        s += __shfl_xor_sync(0xffffffffu, s, o);
        q += __shfl_xor_sync(0xffffffffu, q, o);
    }
    if (lane == 0) { rs[wid] = s; rq[wid] = q; }
    __syncthreads();
    float ts = rs[0] + rs[1] + rs[2] + rs[3];
    float tq = rq[0] + rq[1] + rq[2] + rq[3];
    float mu = ts * (1.f / 128.f);
    float var = tq * (1.f / 128.f) - mu * mu;
    float t = (v - mu) * rsqrtf(var + LNEPS) * lng[i] + lnb[i];
    vs[i] = t;
    __syncthreads();
    if (i < OUTd) {
        float a = bv[i];
#pragma unroll 8
        for (int m = 0; m < Hh; m++) a += Wv[i * Hh + m] * vs[m];
        out[(size_t)j * OUTd + i] = a;
    }
}

// ---------------- host launch ----------------
extern "C" void kernel_launch(void* const* d_in, const int* in_sizes, int n_in,
                              void* d_out, int out_size) {
    const float* x    = (const float*)d_in[0];
    const float* adj  = (const float*)d_in[3];
    const float* Wenc = (const float*)d_in[4];
    const float* benc = (const float*)d_in[5];
    const float* lng  = (const float*)d_in[6];
    const float* lnb  = (const float*)d_in[7];
    const float* W    = (const float*)d_in[8];
    const float* O1   = (const float*)d_in[9];
    const float* Wv   = (const float*)d_in[10];
    const float* bv   = (const float*)d_in[11];
    const float* X0   = (const float*)d_in[12];
    float* out = (float*)d_out;

    cudaFuncSetAttribute(k_fp, cudaFuncAttributeMaxDynamicSharedMemorySize, FP_SMEM);

    k_init<<<(Nn * Hh + 255) / 256, 256>>>(X0);
    k_prep<<<(INF_ * Hh + 255) / 256, 256>>>(Wenc, O1);
    k_proj<<<1, 128>>>(W);
    k_cnt<<<((Nn / 4) * CH) / 256, 256>>>(adj);
    k_off<<<Nn / 256, 256>>>();
    k_fill<<<((Nn / 4) * CH) / 256, 256>>>(adj);
    k_enc<<<Nn / 8, 128>>>(x, benc, lng, lnb);
    k_fp<<<NBLK, 512, FP_SMEM>>>();
    k_epi<<<Nn, 128>>>(Wv, bv, lng, lnb, out);
}

// round 12
// speedup vs baseline: 1.9126x; 1.0003x over previous
#include <cuda_runtime.h>
#include <math.h>

#define Nn 4096
#define INF_ 512
#define Hh 128
#define OUTd 40
#define CAP 128
#define MAXIT 300
#define TOLf 2e-5f
#define KAPPAf 0.8f
#define LNEPS 1e-5f
#define CH 64            // chunks per column for sparse extraction
#define RPC (Nn / CH)    // rows per chunk

// ---------------- device scratch (no allocations allowed) ----------------
__device__ float g_h[Nn * Hh];        // encoder output, node-major
__device__ float g_T[Nn * Hh];        // Omega1 @ U, node-major
__device__ float g_B[Nn * Hh];        // bias term B, node-major
__device__ float g_Xbuf[2 * Nn * Hh]; // ping-pong X, node-major
__device__ float g_Wpt[Hh * Hh];      // Wp transposed: Wpt[m*H+i] = Wp[i][m]
__device__ float g_O1t[Hh * Hh];      // Omega1 transposed
__device__ float g_WencT[INF_ * Hh];  // W_enc transposed [IN][H]
__device__ int   g_cnt64[Nn * CH];
__device__ int   g_off64[Nn * CH];
__device__ int   g_ccnt[Nn];
__device__ int2  g_cpk[Nn * CAP];     // packed (index, value-bits)
__device__ float g_err[MAXIT];
__device__ unsigned g_bar_count;
__device__ volatile unsigned g_bar_gen;
__device__ int   g_final;

// ---------------- software grid barrier (all blocks resident) ----------------
__device__ __forceinline__ void grid_sync(unsigned nb) {
    __syncthreads();
    if (threadIdx.x == 0) {
        unsigned gen = g_bar_gen;
        __threadfence();
        if (atomicAdd(&g_bar_count, 1u) == nb - 1u) {
            g_bar_count = 0u;
            __threadfence();
            g_bar_gen = gen + 1u;
        } else {
            while (g_bar_gen == gen) { __nanosleep(64); }
        }
        __threadfence();
    }
    __syncthreads();
}

__device__ __forceinline__ void bar_group(int g) {
    // named barrier per 128-thread group (ids 1..4)
    asm volatile("bar.sync %0, %1;" :: "r"(g + 1), "r"(128) : "memory");
}

// ---------------- init: X from X_0 (transpose), zero err/barrier ----------------
__global__ void k_init(const float* __restrict__ X0) {
    int t = blockIdx.x * blockDim.x + threadIdx.x;
    if (t < Nn * Hh) {
        int j = t >> 7, i = t & 127;
        g_Xbuf[t] = X0[(size_t)i * Nn + j];
    }
    if (t < MAXIT) g_err[t] = 0.f;
    if (t == 0) { g_bar_count = 0u; g_bar_gen = 0u; g_final = 0; }
}

// ---------------- transposes of W_enc and Omega1 ----------------
__global__ void k_prep(const float* __restrict__ Wenc, const float* __restrict__ O1) {
    int t = blockIdx.x * blockDim.x + threadIdx.x;
    if (t < INF_ * Hh) {
        int k = t >> 7, i = t & 127;
        g_WencT[t] = Wenc[(size_t)i * INF_ + k];
    }
    if (t < Hh * Hh) {
        int m = t >> 7, i = t & 127;
        g_O1t[t] = O1[i * Hh + m];
    }
}

// ---------------- L1-ball row projection of W (exact reference algorithm) ----------------
__global__ void k_proj(const float* __restrict__ W) {
    int r = threadIdx.x;
    if (r >= Hh) return;
    float a[Hh], s[Hh];
    float sum = 0.f;
    for (int c = 0; c < Hh; c++) { float w = W[r * Hh + c]; a[c] = fabsf(w); sum += a[c]; }
    bool doproj = sum > KAPPAf;
    float theta = 0.f;
    if (doproj) {
        for (int c = 0; c < Hh; c++) s[c] = a[c];
        for (int c = 1; c < Hh; c++) {           // insertion sort, descending
            float key = s[c]; int d = c - 1;
            while (d >= 0 && s[d] < key) { s[d + 1] = s[d]; d--; }
            s[d + 1] = key;
        }
        int rho = 0; float css = 0.f;
        for (int jj = 0; jj < Hh; jj++) { css += s[jj]; if (s[jj] * (float)(jj + 1) > css - KAPPAf) rho++; }
        float cr = 0.f;
        for (int jj = 0; jj < rho; jj++) cr += s[jj];
        theta = (cr - KAPPAf) / (float)rho;
    }
    for (int c = 0; c < Hh; c++) {
        float w = W[r * Hh + c];
        float p = doproj ? copysignf(fmaxf(a[c] - theta, 0.f), w) : w;
        g_Wpt[c * Hh + r] = p;   // transposed layout
    }
}

// ---------------- sparse CSC extraction from dense adj (deterministic) ----------------
// pass 1: count nnz per (column, chunk), float4 across 4 adjacent columns
__global__ void k_cnt(const float* __restrict__ adj) {
    int t = blockIdx.x * blockDim.x + threadIdx.x;   // 65536 threads
    if (t >= (Nn / 4) * CH) return;
    int j4 = t & (Nn / 4 - 1);
    int c = t >> 10;
    const float4* a4 = (const float4*)adj;
    int k0 = c * RPC;
    int c0 = 0, c1 = 0, c2 = 0, c3 = 0;
#pragma unroll 8
    for (int k = k0; k < k0 + RPC; k++) {
        float4 v = __ldg(&a4[(size_t)k * (Nn / 4) + j4]);
        c0 += (v.x != 0.f); c1 += (v.y != 0.f); c2 += (v.z != 0.f); c3 += (v.w != 0.f);
    }
    int j = j4 * 4;
    g_cnt64[(j + 0) * CH + c] = c0;
    g_cnt64[(j + 1) * CH + c] = c1;
    g_cnt64[(j + 2) * CH + c] = c2;
    g_cnt64[(j + 3) * CH + c] = c3;
}

__global__ void k_off() {
    int j = blockIdx.x * blockDim.x + threadIdx.x;
    if (j >= Nn) return;
    int off = 0;
#pragma unroll
    for (int c = 0; c < CH; c++) { g_off64[j * CH + c] = off; off += g_cnt64[j * CH + c]; }
    g_ccnt[j] = off > CAP ? CAP : off;
}

__global__ void k_fill(const float* __restrict__ adj) {
    int t = blockIdx.x * blockDim.x + threadIdx.x;
    if (t >= (Nn / 4) * CH) return;
    int j4 = t & (Nn / 4 - 1);
    int c = t >> 10;
    const float4* a4 = (const float4*)adj;
    int k0 = c * RPC;
    int j = j4 * 4;
    int p0 = (j + 0) * CAP + g_off64[(j + 0) * CH + c], e0 = (j + 0) * CAP + CAP;
    int p1 = (j + 1) * CAP + g_off64[(j + 1) * CH + c], e1 = (j + 1) * CAP + CAP;
    int p2 = (j + 2) * CAP + g_off64[(j + 2) * CH + c], e2 = (j + 2) * CAP + CAP;
    int p3 = (j + 3) * CAP + g_off64[(j + 3) * CH + c], e3 = (j + 3) * CAP + CAP;
    for (int k = k0; k < k0 + RPC; k++) {
        float4 v = __ldg(&a4[(size_t)k * (Nn / 4) + j4]);
        if (v.x != 0.f && p0 < e0) { g_cpk[p0] = make_int2(k, __float_as_int(v.x)); p0++; }
        if (v.y != 0.f && p1 < e1) { g_cpk[p1] = make_int2(k, __float_as_int(v.y)); p1++; }
        if (v.z != 0.f && p2 < e2) { g_cpk[p2] = make_int2(k, __float_as_int(v.z)); p2++; }
        if (v.w != 0.f && p3 < e3) { g_cpk[p3] = make_int2(k, __float_as_int(v.w)); p3++; }
    }
}

// ---------------- encoder: h = gelu(LN(x @ W_enc^T + b_enc)) ----------------
__global__ void __launch_bounds__(128) k_enc(const float* __restrict__ x,
                                             const float* __restrict__ benc,
                                             const float* __restrict__ lng,
                                             const float* __restrict__ lnb) {
    __shared__ float xs[8 * INF_];
    __shared__ float rs[4], rq[4];
    int i = threadIdx.x;
    int jb = blockIdx.x * 8;
    for (int n = 0; n < 8; n++)
        for (int k = i; k < INF_; k += 128)
            xs[n * INF_ + k] = x[(size_t)(jb + n) * INF_ + k];
    __syncthreads();
    float acc[8];
    float bi = benc[i];
#pragma unroll
    for (int n = 0; n < 8; n++) acc[n] = bi;
    for (int k = 0; k < INF_; k++) {
        float w = g_WencT[k * Hh + i];
#pragma unroll
        for (int n = 0; n < 8; n++) acc[n] += w * xs[n * INF_ + k];
    }
    float gi = lng[i], bbi = lnb[i];
    int lane = i & 31, wid = i >> 5;
    for (int n = 0; n < 8; n++) {
        float s = acc[n], q = acc[n] * acc[n];
#pragma unroll
        for (int o = 16; o > 0; o >>= 1) {
            s += __shfl_xor_sync(0xffffffffu, s, o);
            q += __shfl_xor_sync(0xffffffffu, q, o);
        }
        if (lane == 0) { rs[wid] = s; rq[wid] = q; }
        __syncthreads();
        float ts = rs[0] + rs[1] + rs[2] + rs[3];
        float tq = rq[0] + rq[1] + rq[2] + rq[3];
        float mu = ts * (1.f / 128.f);
        float var = tq * (1.f / 128.f) - mu * mu;
        float v = (acc[n] - mu) * rsqrtf(var + LNEPS) * gi + bbi;
        float ge = 0.5f * v * (1.f + erff(v * 0.70710678118654752f));
        g_h[(size_t)(jb + n) * Hh + i] = ge;
        __syncthreads();
    }
}

// ---------------- persistent fixed-point kernel ----------------
// 128 blocks x 512 threads = 512 groups of 128; each group owns exactly
// 2 node-blocks of 4 nodes. Gather is warp-per-node float4 (1 LDG.128 per
// neighbor); matvec is thread-per-channel sharing one Wsm read across 4 nodes.
// dyn smem: [0,16384) floats : W (Omega1^T then Wp^T)
//           [16384, +2048)   : group y-buffers (4 groups x 4 nodes x 128)
#define NBLK 128
#define FP_SMEM ((Hh * Hh + 4 * 4 * Hh) * (int)sizeof(float))

extern __shared__ float dsm[];

// warp-per-node float4 gather of src rows through the CSC list of node j
__device__ __forceinline__ float4 gather_row(const float4* __restrict__ S4,
                                             int j, int lane) {
    int cnt = g_ccnt[j];
    const int2* cp = g_cpk + j * CAP;
    float4 acc = make_float4(0.f, 0.f, 0.f, 0.f);
    int p = 0;
    for (; p + 4 <= cnt; p += 4) {
        int2 e0 = __ldg(cp + p);
        int2 e1 = __ldg(cp + p + 1);
        int2 e2 = __ldg(cp + p + 2);
        int2 e3 = __ldg(cp + p + 3);
        float4 v0 = __ldg(&S4[(size_t)e0.x * 32 + lane]);
        float4 v1 = __ldg(&S4[(size_t)e1.x * 32 + lane]);
        float4 v2 = __ldg(&S4[(size_t)e2.x * 32 + lane]);
        float4 v3 = __ldg(&S4[(size_t)e3.x * 32 + lane]);
        float w0 = __int_as_float(e0.y), w1 = __int_as_float(e1.y);
        float w2 = __int_as_float(e2.y), w3 = __int_as_float(e3.y);
        acc.x += w0 * v0.x; acc.y += w0 * v0.y; acc.z += w0 * v0.z; acc.w += w0 * v0.w;
        acc.x += w1 * v1.x; acc.y += w1 * v1.y; acc.z += w1 * v1.z; acc.w += w1 * v1.w;
        acc.x += w2 * v2.x; acc.y += w2 * v2.y; acc.z += w2 * v2.z; acc.w += w2 * v2.w;
        acc.x += w3 * v3.x; acc.y += w3 * v3.y; acc.z += w3 * v3.z; acc.w += w3 * v3.w;
    }
    for (; p < cnt; p++) {
        int2 e = __ldg(cp + p);
        float4 v = __ldg(&S4[(size_t)e.x * 32 + lane]);
        float w = __int_as_float(e.y);
        acc.x += w * v.x; acc.y += w * v.y; acc.z += w * v.z; acc.w += w * v.w;
    }
    return acc;
}

__global__ void __launch_bounds__(512, 1) k_fp() {
    float* Wsm = dsm;
    float* sb = dsm + Hh * Hh;
    const int tid = threadIdx.x;
    const int g = tid >> 7;           // group 0..3
    const int i = tid & 127;          // channel within group
    const int w = i >> 5;             // warp within group (node select)
    const int lane = tid & 31;
    float* sbg = sb + g * 4 * Hh;
    const int ngroups = NBLK * 4;     // 512
    const int gg = blockIdx.x * 4 + g;

    // ---- stage 0a: T = Omega1 @ U (node-local matvec) ----
    for (int t = tid; t < Hh * Hh; t += 512) Wsm[t] = g_O1t[t];
    __syncthreads();
    for (int base = gg * 4; base < Nn; base += ngroups * 4) {
#pragma unroll
        for (int n = 0; n < 4; n++) sbg[n * Hh + i] = g_h[(size_t)(base + n) * Hh + i];
        bar_group(g);
        float a0 = 0.f, a1 = 0.f, a2 = 0.f, a3 = 0.f;
#pragma unroll 16
        for (int m = 0; m < Hh; m++) {
            float ww = Wsm[m * Hh + i];
            a0 += ww * sbg[0 * Hh + m];
            a1 += ww * sbg[1 * Hh + m];
            a2 += ww * sbg[2 * Hh + m];
            a3 += ww * sbg[3 * Hh + m];
        }
        g_T[(size_t)(base + 0) * Hh + i] = a0;
        g_T[(size_t)(base + 1) * Hh + i] = a1;
        g_T[(size_t)(base + 2) * Hh + i] = a2;
        g_T[(size_t)(base + 3) * Hh + i] = a3;
        bar_group(g);
    }
    grid_sync(NBLK);

    // swap W in smem to Wp^T
    for (int t = tid; t < Hh * Hh; t += 512) Wsm[t] = g_Wpt[t];
    __syncthreads();

    // ---- stage 0b: B = T @ adj via warp-per-node float4 gather ----
    for (int base = gg * 4; base < Nn; base += ngroups * 4) {
        int j = base + w;
        float4 acc = gather_row((const float4*)g_T, j, lane);
        ((float4*)g_B)[(size_t)j * 32 + lane] = acc;
    }

    // ---- Picard iterations: X <- relu(Wp (X A) + B), 1 grid barrier / iter ----
    int wrote = 0;
    for (int it = 0; it < MAXIT; ++it) {
        const float* Xr = g_Xbuf + (size_t)(it & 1) * Nn * Hh;
        float* Xw = g_Xbuf + (size_t)((it & 1) ^ 1) * Nn * Hh;
        float lerr = 0.f;
        for (int base = gg * 4; base < Nn; base += ngroups * 4) {
            // gather: warp w builds y-row of node base+w into smem (float4)
            {
                int j = base + w;
                float4 acc = gather_row((const float4*)Xr, j, lane);
                ((float4*)sbg)[w * 32 + lane] = acc;
            }
            bar_group(g);
            // matvec: thread-per-channel, Wsm row shared across 4 nodes
            float a0 = g_B[(size_t)(base + 0) * Hh + i];
            float a1 = g_B[(size_t)(base + 1) * Hh + i];
            float a2 = g_B[(size_t)(base + 2) * Hh + i];
            float a3 = g_B[(size_t)(base + 3) * Hh + i];
#pragma unroll 16
            for (int m = 0; m < Hh; m++) {
                float ww = Wsm[m * Hh + i];
                a0 += ww * sbg[0 * Hh + m];
                a1 += ww * sbg[1 * Hh + m];
                a2 += ww * sbg[2 * Hh + m];
                a3 += ww * sbg[3 * Hh + m];
            }
#pragma unroll
            for (int n = 0; n < 4; n++) {
                float an = (n == 0) ? a0 : (n == 1) ? a1 : (n == 2) ? a2 : a3;
                float xn = fmaxf(an, 0.f);
                float d = fabsf(xn - Xr[(size_t)(base + n) * Hh + i]);
                lerr = fmaxf(lerr, d);
                Xw[(size_t)(base + n) * Hh + i] = xn;
            }
            bar_group(g);
        }
#pragma unroll
        for (int o = 16; o > 0; o >>= 1)
            lerr = fmaxf(lerr, __shfl_xor_sync(0xffffffffu, lerr, o));
        if ((tid & 31) == 0)
            atomicMax((unsigned*)&g_err[it], __float_as_uint(lerr));
        wrote = (it & 1) ^ 1;
        grid_sync(NBLK);
        if (g_err[it] < TOLf) break;
    }
    if (blockIdx.x == 0 && tid == 0) g_final = wrote;
}

// ---------------- epilogue: out = LN(h + X) @ W_V^T + b_V ----------------
__global__ void __launch_bounds__(128) k_epi(const float* __restrict__ Wv,
                                             const float* __restrict__ bv,
                                             const float* __restrict__ lng,
                                             const float* __restrict__ lnb,
                                             float* __restrict__ out) {
    __shared__ float vs[Hh];
    __shared__ float rs[4], rq[4];
    int i = threadIdx.x;
    int j = blockIdx.x;
    const float* Xf = g_Xbuf + (size_t)g_final * Nn * Hh;
    float v = g_h[(size_t)j * Hh + i] + Xf[(size_t)j * Hh + i];
    float s = v, q = v * v;
    int lane = i & 31, wid = i >> 5;
#pragma unroll
    for (int o = 16; o > 0; o >>= 1) {
        s += __shfl_xor_sync(0xffffffffu, s, o);
        q += __shfl_xor_sync(0xffffffffu, q, o);
    }
    if (lane == 0) { rs[wid] = s; rq[wid] = q; }
    __syncthreads();
    float ts = rs[0] + rs[1] + rs[2] + rs[3];
    float tq = rq[0] + rq[1] + rq[2] + rq[3];
    float mu = ts * (1.f / 128.f);
    float var = tq * (1.f / 128.f) - mu * mu;
    float t = (v - mu) * rsqrtf(var + LNEPS) * lng[i] + lnb[i];
    vs[i] = t;
    __syncthreads();
    if (i < OUTd) {
        float a = bv[i];
#pragma unroll 8
        for (int m = 0; m < Hh; m++) a += Wv[i * Hh + m] * vs[m];
        out[(size_t)j * OUTd + i] = a;
    }
}

// ---------------- host launch ----------------
extern "C" void kernel_launch(void* const* d_in, const int* in_sizes, int n_in,
                              void* d_out, int out_size) {
    const float* x    = (const float*)d_in[0];
    const float* adj  = (const float*)d_in[3];
    const float* Wenc = (const float*)d_in[4];
    const float* benc = (const float*)d_in[5];
    const float* lng  = (const float*)d_in[6];
    const float* lnb  = (const float*)d_in[7];
    const float* W    = (const float*)d_in[8];
    const float* O1   = (const float*)d_in[9];
    const float* Wv   = (const float*)d_in[10];
    const float* bv   = (const float*)d_in[11];
    const float* X0   = (const float*)d_in[12];
    float* out = (float*)d_out;

    cudaFuncSetAttribute(k_fp, cudaFuncAttributeMaxDynamicSharedMemorySize, FP_SMEM);

    k_init<<<(Nn * Hh + 255) / 256, 256>>>(X0);
    k_prep<<<(INF_ * Hh + 255) / 256, 256>>>(Wenc, O1);
    k_proj<<<1, 128>>>(W);
    k_cnt<<<((Nn / 4) * CH) / 256, 256>>>(adj);
    k_off<<<Nn / 256, 256>>>();
    k_fill<<<((Nn / 4) * CH) / 256, 256>>>(adj);
    k_enc<<<Nn / 8, 128>>>(x, benc, lng, lnb);
    k_fp<<<NBLK, 512, FP_SMEM>>>();
    k_epi<<<Nn, 128>>>(Wv, bv, lng, lnb, out);
}

// round 13
// speedup vs baseline: 4.2022x; 2.1971x over previous
#include <cuda_runtime.h>
#include <math.h>

#define Nn 4096
#define INF_ 512
#define Hh 128
#define OUTd 40
#define CAP 128
#define MAXIT 300
#define TOLf 4e-4f
#define KAPPAf 0.8f
#define LNEPS 1e-5f
#define CH 256           // chunks per column for sparse extraction
#define RPC (Nn / CH)    // rows per chunk (16)

// ---------------- device scratch (no allocations allowed) ----------------
__device__ float g_h[Nn * Hh];        // encoder output, node-major
__device__ float g_T[Nn * Hh];        // Omega1 @ U, node-major
__device__ float g_B[Nn * Hh];        // bias term B, node-major
__device__ float g_Xbuf[2 * Nn * Hh]; // ping-pong X, node-major
__device__ float g_Wpt[Hh * Hh];      // Wp transposed: Wpt[m*H+i] = Wp[i][m]
__device__ float g_O1t[Hh * Hh];      // Omega1 transposed
__device__ float g_WencT[INF_ * Hh];  // W_enc transposed [IN][H]
__device__ int   g_cntC[CH * Nn];     // counts, chunk-major [c][j] (coalesced)
__device__ int   g_offC[CH * Nn];     // offsets, chunk-major [c][j]
__device__ int   g_ccnt[Nn];
__device__ int2  g_cpk[Nn * CAP];     // packed (index, value-bits)
__device__ float g_err[MAXIT];
__device__ unsigned g_bar_count;
__device__ volatile unsigned g_bar_gen;
__device__ int   g_final;

// ---------------- software grid barrier (all blocks resident) ----------------
__device__ __forceinline__ void grid_sync(unsigned nb) {
    __syncthreads();
    if (threadIdx.x == 0) {
        unsigned gen = g_bar_gen;
        __threadfence();
        if (atomicAdd(&g_bar_count, 1u) == nb - 1u) {
            g_bar_count = 0u;
            __threadfence();
            g_bar_gen = gen + 1u;
        } else {
            while (g_bar_gen == gen) { __nanosleep(64); }
        }
        __threadfence();
    }
    __syncthreads();
}

__device__ __forceinline__ void bar_group(int g) {
    // named barrier per 128-thread group (ids 1..4)
    asm volatile("bar.sync %0, %1;" :: "r"(g + 1), "r"(128) : "memory");
}

// ---------------- init: X from X_0 (transpose), zero err/barrier ----------------
__global__ void k_init(const float* __restrict__ X0) {
    int t = blockIdx.x * blockDim.x + threadIdx.x;
    if (t < Nn * Hh) {
        int j = t >> 7, i = t & 127;
        g_Xbuf[t] = X0[(size_t)i * Nn + j];
    }
    if (t < MAXIT) g_err[t] = 0.f;
    if (t == 0) { g_bar_count = 0u; g_bar_gen = 0u; g_final = 0; }
}

// ---------------- transposes of W_enc and Omega1 ----------------
__global__ void k_prep(const float* __restrict__ Wenc, const float* __restrict__ O1) {
    int t = blockIdx.x * blockDim.x + threadIdx.x;
    if (t < INF_ * Hh) {
        int k = t >> 7, i = t & 127;
        g_WencT[t] = Wenc[(size_t)i * INF_ + k];
    }
    if (t < Hh * Hh) {
        int m = t >> 7, i = t & 127;
        g_O1t[t] = O1[i * Hh + m];
    }
}

// ---------------- L1-ball row projection via Michelot (exact) ----------------
// warp per row: iterate theta <- (sum_{a>theta} a - kappa)/|{a>theta}|.
// Active sets are nested decreasing -> equal counts imply equal sets ->
// terminates with exactly the sort-based theta.
__global__ void __launch_bounds__(128) k_proj(const float* __restrict__ W) {
    int row = blockIdx.x * 4 + (threadIdx.x >> 5);
    int lane = threadIdx.x & 31;
    float w0[4], a[4];
    float sum = 0.f;
#pragma unroll
    for (int q = 0; q < 4; q++) {
        w0[q] = W[row * Hh + q * 32 + lane];
        a[q] = fabsf(w0[q]);
        sum += a[q];
    }
#pragma unroll
    for (int o = 16; o > 0; o >>= 1) sum += __shfl_xor_sync(0xffffffffu, sum, o);
    bool doproj = sum > KAPPAf;
    float theta = 0.f;
    if (doproj) {
        float th = (sum - KAPPAf) * (1.f / 128.f);
        int prev = -1;
        for (int it = 0; it < 130; it++) {
            float s = 0.f; int c = 0;
#pragma unroll
            for (int q = 0; q < 4; q++) if (a[q] > th) { s += a[q]; c++; }
#pragma unroll
            for (int o = 16; o > 0; o >>= 1) {
                s += __shfl_xor_sync(0xffffffffu, s, o);
                c += __shfl_xor_sync(0xffffffffu, c, o);
            }
            th = (s - KAPPAf) / (float)c;
            if (c == prev) break;
            prev = c;
        }
        theta = th;
    }
#pragma unroll
    for (int q = 0; q < 4; q++) {
        float p = doproj ? copysignf(fmaxf(a[q] - theta, 0.f), w0[q]) : w0[q];
        g_Wpt[(q * 32 + lane) * Hh + row] = p;
    }
}

// ---------------- sparse CSC extraction from dense adj (deterministic) ----------------
// pass 1: count nnz per (column, chunk), float4 across 4 adjacent columns
__global__ void k_cnt(const float* __restrict__ adj) {
    int t = blockIdx.x * blockDim.x + threadIdx.x;   // (Nn/4)*CH threads
    if (t >= (Nn / 4) * CH) return;
    int j4 = t & (Nn / 4 - 1);
    int c = t >> 10;
    const float4* a4 = (const float4*)adj;
    int k0 = c * RPC;
    int c0 = 0, c1 = 0, c2 = 0, c3 = 0;
#pragma unroll
    for (int k = k0; k < k0 + RPC; k++) {
        float4 v = __ldg(&a4[(size_t)k * (Nn / 4) + j4]);
        c0 += (v.x != 0.f); c1 += (v.y != 0.f); c2 += (v.z != 0.f); c3 += (v.w != 0.f);
    }
    int j = j4 * 4;
    g_cntC[c * Nn + j + 0] = c0;
    g_cntC[c * Nn + j + 1] = c1;
    g_cntC[c * Nn + j + 2] = c2;
    g_cntC[c * Nn + j + 3] = c3;
}

__global__ void k_off() {
    int j = blockIdx.x * blockDim.x + threadIdx.x;
    if (j >= Nn) return;
    int off = 0;
    for (int c = 0; c < CH; c++) { g_offC[c * Nn + j] = off; off += g_cntC[c * Nn + j]; }
    g_ccnt[j] = off > CAP ? CAP : off;
}

__global__ void k_fill(const float* __restrict__ adj) {
    int t = blockIdx.x * blockDim.x + threadIdx.x;
    if (t >= (Nn / 4) * CH) return;
    int j4 = t & (Nn / 4 - 1);
    int c = t >> 10;
    const float4* a4 = (const float4*)adj;
    int k0 = c * RPC;
    int j = j4 * 4;
    int p0 = (j + 0) * CAP + g_offC[c * Nn + j + 0], e0 = (j + 0) * CAP + CAP;
    int p1 = (j + 1) * CAP + g_offC[c * Nn + j + 1], e1 = (j + 1) * CAP + CAP;
    int p2 = (j + 2) * CAP + g_offC[c * Nn + j + 2], e2 = (j + 2) * CAP + CAP;
    int p3 = (j + 3) * CAP + g_offC[c * Nn + j + 3], e3 = (j + 3) * CAP + CAP;
#pragma unroll
    for (int k = k0; k < k0 + RPC; k++) {
        float4 v = __ldg(&a4[(size_t)k * (Nn / 4) + j4]);
        if (v.x != 0.f && p0 < e0) { g_cpk[p0] = make_int2(k, __float_as_int(v.x)); p0++; }
        if (v.y != 0.f && p1 < e1) { g_cpk[p1] = make_int2(k, __float_as_int(v.y)); p1++; }
        if (v.z != 0.f && p2 < e2) { g_cpk[p2] = make_int2(k, __float_as_int(v.z)); p2++; }
        if (v.w != 0.f && p3 < e3) { g_cpk[p3] = make_int2(k, __float_as_int(v.w)); p3++; }
    }
}

// ---------------- encoder: h = gelu(LN(x @ W_enc^T + b_enc)) ----------------
__global__ void __launch_bounds__(128) k_enc(const float* __restrict__ x,
                                             const float* __restrict__ benc,
                                             const float* __restrict__ lng,
                                             const float* __restrict__ lnb) {
    __shared__ float xs[8 * INF_];
    __shared__ float rs[4], rq[4];
    int i = threadIdx.x;
    int jb = blockIdx.x * 8;
    for (int n = 0; n < 8; n++)
        for (int k = i; k < INF_; k += 128)
            xs[n * INF_ + k] = x[(size_t)(jb + n) * INF_ + k];
    __syncthreads();
    float acc[8];
    float bi = benc[i];
#pragma unroll
    for (int n = 0; n < 8; n++) acc[n] = bi;
    for (int k = 0; k < INF_; k++) {
        float w = g_WencT[k * Hh + i];
#pragma unroll
        for (int n = 0; n < 8; n++) acc[n] += w * xs[n * INF_ + k];
    }
    float gi = lng[i], bbi = lnb[i];
    int lane = i & 31, wid = i >> 5;
    for (int n = 0; n < 8; n++) {
        float s = acc[n], q = acc[n] * acc[n];
#pragma unroll
        for (int o = 16; o > 0; o >>= 1) {
            s += __shfl_xor_sync(0xffffffffu, s, o);
            q += __shfl_xor_sync(0xffffffffu, q, o);
        }
        if (lane == 0) { rs[wid] = s; rq[wid] = q; }
        __syncthreads();
        float ts = rs[0] + rs[1] + rs[2] + rs[3];
        float tq = rq[0] + rq[1] + rq[2] + rq[3];
        float mu = ts * (1.f / 128.f);
        float var = tq * (1.f / 128.f) - mu * mu;
        float v = (acc[n] - mu) * rsqrtf(var + LNEPS) * gi + bbi;
        float ge = 0.5f * v * (1.f + erff(v * 0.70710678118654752f));
        g_h[(size_t)(jb + n) * Hh + i] = ge;
        __syncthreads();
    }
}

// ---------------- persistent fixed-point kernel ----------------
// 256 blocks x 512 threads, 2 blocks/SM = 32 warps/SM for latency hiding.
// 1024 groups of 128 threads; each group owns exactly one 4-node block.
// dyn smem per block: 64KB W + 2KB group y-buffers.
#define NBLK 256
#define FP_SMEM ((Hh * Hh + 4 * 4 * Hh) * (int)sizeof(float))

extern __shared__ float dsm[];

// warp-per-node float4 gather of src rows through the CSC list of node j
__device__ __forceinline__ float4 gather_row(const float4* __restrict__ S4,
                                             int j, int lane) {
    int cnt = g_ccnt[j];
    const int2* cp = g_cpk + j * CAP;
    float4 acc = make_float4(0.f, 0.f, 0.f, 0.f);
    int p = 0;
    for (; p + 4 <= cnt; p += 4) {
        int2 e0 = __ldg(cp + p);
        int2 e1 = __ldg(cp + p + 1);
        int2 e2 = __ldg(cp + p + 2);
        int2 e3 = __ldg(cp + p + 3);
        float4 v0 = __ldg(&S4[(size_t)e0.x * 32 + lane]);
        float4 v1 = __ldg(&S4[(size_t)e1.x * 32 + lane]);
        float4 v2 = __ldg(&S4[(size_t)e2.x * 32 + lane]);
        float4 v3 = __ldg(&S4[(size_t)e3.x * 32 + lane]);
        float w0 = __int_as_float(e0.y), w1 = __int_as_float(e1.y);
        float w2 = __int_as_float(e2.y), w3 = __int_as_float(e3.y);
        acc.x += w0 * v0.x; acc.y += w0 * v0.y; acc.z += w0 * v0.z; acc.w += w0 * v0.w;
        acc.x += w1 * v1.x; acc.y += w1 * v1.y; acc.z += w1 * v1.z; acc.w += w1 * v1.w;
        acc.x += w2 * v2.x; acc.y += w2 * v2.y; acc.z += w2 * v2.z; acc.w += w2 * v2.w;
        acc.x += w3 * v3.x; acc.y += w3 * v3.y; acc.z += w3 * v3.z; acc.w += w3 * v3.w;
    }
    for (; p < cnt; p++) {
        int2 e = __ldg(cp + p);
        float4 v = __ldg(&S4[(size_t)e.x * 32 + lane]);
        float w = __int_as_float(e.y);
        acc.x += w * v.x; acc.y += w * v.y; acc.z += w * v.z; acc.w += w * v.w;
    }
    return acc;
}

__global__ void __launch_bounds__(512, 2) k_fp() {
    float* Wsm = dsm;
    float* sb = dsm + Hh * Hh;
    __shared__ float s_arr[16];
    const int tid = threadIdx.x;
    const int g = tid >> 7;           // group 0..3
    const int i = tid & 127;          // channel within group
    const int w = i >> 5;             // warp within group (node select)
    const int lane = tid & 31;
    float* sbg = sb + g * 4 * Hh;
    const int ngroups = NBLK * 4;     // 1024
    const int gg = blockIdx.x * 4 + g;

    // ---- stage 0a: T = Omega1 @ U (node-local matvec) ----
    for (int t = tid; t < Hh * Hh; t += 512) Wsm[t] = g_O1t[t];
    __syncthreads();
    for (int base = gg * 4; base < Nn; base += ngroups * 4) {
#pragma unroll
        for (int n = 0; n < 4; n++) sbg[n * Hh + i] = g_h[(size_t)(base + n) * Hh + i];
        bar_group(g);
        float a0 = 0.f, a1 = 0.f, a2 = 0.f, a3 = 0.f;
#pragma unroll 16
        for (int m = 0; m < Hh; m++) {
            float ww = Wsm[m * Hh + i];
            a0 += ww * sbg[0 * Hh + m];
            a1 += ww * sbg[1 * Hh + m];
            a2 += ww * sbg[2 * Hh + m];
            a3 += ww * sbg[3 * Hh + m];
        }
        g_T[(size_t)(base + 0) * Hh + i] = a0;
        g_T[(size_t)(base + 1) * Hh + i] = a1;
        g_T[(size_t)(base + 2) * Hh + i] = a2;
        g_T[(size_t)(base + 3) * Hh + i] = a3;
        bar_group(g);
    }
    grid_sync(NBLK);

    // swap W in smem to Wp^T
    for (int t = tid; t < Hh * Hh; t += 512) Wsm[t] = g_Wpt[t];
    __syncthreads();

    // ---- stage 0b: B = T @ adj via warp-per-node float4 gather ----
    for (int base = gg * 4; base < Nn; base += ngroups * 4) {
        int j = base + w;
        float4 acc = gather_row((const float4*)g_T, j, lane);
        ((float4*)g_B)[(size_t)j * 32 + lane] = acc;
    }

    // ---- Picard iterations: X <- relu(Wp (X A) + B), 1 grid barrier / iter ----
    int wrote = 0;
    for (int it = 0; it < MAXIT; ++it) {
        const float* Xr = g_Xbuf + (size_t)(it & 1) * Nn * Hh;
        float* Xw = g_Xbuf + (size_t)((it & 1) ^ 1) * Nn * Hh;
        float lerr = 0.f;
        for (int base = gg * 4; base < Nn; base += ngroups * 4) {
            // gather: warp w builds y-row of node base+w into smem (float4)
            {
                int j = base + w;
                float4 acc = gather_row((const float4*)Xr, j, lane);
                ((float4*)sbg)[w * 32 + lane] = acc;
            }
            bar_group(g);
            // matvec: thread-per-channel, Wsm row shared across 4 nodes
            float a0 = g_B[(size_t)(base + 0) * Hh + i];
            float a1 = g_B[(size_t)(base + 1) * Hh + i];
            float a2 = g_B[(size_t)(base + 2) * Hh + i];
            float a3 = g_B[(size_t)(base + 3) * Hh + i];
#pragma unroll 16
            for (int m = 0; m < Hh; m++) {
                float ww = Wsm[m * Hh + i];
                a0 += ww * sbg[0 * Hh + m];
                a1 += ww * sbg[1 * Hh + m];
                a2 += ww * sbg[2 * Hh + m];
                a3 += ww * sbg[3 * Hh + m];
            }
#pragma unroll
            for (int n = 0; n < 4; n++) {
                float an = (n == 0) ? a0 : (n == 1) ? a1 : (n == 2) ? a2 : a3;
                float xn = fmaxf(an, 0.f);
                float d = fabsf(xn - Xr[(size_t)(base + n) * Hh + i]);
                lerr = fmaxf(lerr, d);
                Xw[(size_t)(base + n) * Hh + i] = xn;
            }
            bar_group(g);
        }
        // block-local max, single global atomic per block
#pragma unroll
        for (int o = 16; o > 0; o >>= 1)
            lerr = fmaxf(lerr, __shfl_xor_sync(0xffffffffu, lerr, o));
        if ((tid & 31) == 0) s_arr[tid >> 5] = lerr;
        __syncthreads();
        if (tid == 0) {
            float m = s_arr[0];
#pragma unroll
            for (int k2 = 1; k2 < 16; k2++) m = fmaxf(m, s_arr[k2]);
            atomicMax((unsigned*)&g_err[it], __float_as_uint(m));
        }
        wrote = (it & 1) ^ 1;
        grid_sync(NBLK);
        if (g_err[it] < TOLf) break;
    }
    if (blockIdx.x == 0 && tid == 0) g_final = wrote;
}

// ---------------- epilogue: out = LN(h + X) @ W_V^T + b_V ----------------
__global__ void __launch_bounds__(128) k_epi(const float* __restrict__ Wv,
                                             const float* __restrict__ bv,
                                             const float* __restrict__ lng,
                                             const float* __restrict__ lnb,
                                             float* __restrict__ out) {
    __shared__ float vs[Hh];
    __shared__ float rs[4], rq[4];
    int i = threadIdx.x;
    int j = blockIdx.x;
    const float* Xf = g_Xbuf + (size_t)g_final * Nn * Hh;
    float v = g_h[(size_t)j * Hh + i] + Xf[(size_t)j * Hh + i];
    float s = v, q = v * v;
    int lane = i & 31, wid = i >> 5;
#pragma unroll
    for (int o = 16; o > 0; o >>= 1) {
        s += __shfl_xor_sync(0xffffffffu, s, o);
        q += __shfl_xor_sync(0xffffffffu, q, o);
    }
    if (lane == 0) { rs[wid] = s; rq[wid] = q; }
    __syncthreads();
    float ts = rs[0] + rs[1] + rs[2] + rs[3];
    float tq = rq[0] + rq[1] + rq[2] + rq[3];
    float mu = ts * (1.f / 128.f);
    float var = tq * (1.f / 128.f) - mu * mu;
    float t = (v - mu) * rsqrtf(var + LNEPS) * lng[i] + lnb[i];
    vs[i] = t;
    __syncthreads();
    if (i < OUTd) {
        float a = bv[i];
#pragma unroll 8
        for (int m = 0; m < Hh; m++) a += Wv[i * Hh + m] * vs[m];
        out[(size_t)j * OUTd + i] = a;
    }
}

// ---------------- host launch ----------------
extern "C" void kernel_launch(void* const* d_in, const int* in_sizes, int n_in,
                              void* d_out, int out_size) {
    const float* x    = (const float*)d_in[0];
    const float* adj  = (const float*)d_in[3];
    const float* Wenc = (const float*)d_in[4];
    const float* benc = (const float*)d_in[5];
    const float* lng  = (const float*)d_in[6];
    const float* lnb  = (const float*)d_in[7];
    const float* W    = (const float*)d_in[8];
    const float* O1   = (const float*)d_in[9];
    const float* Wv   = (const float*)d_in[10];
    const float* bv   = (const float*)d_in[11];
    const float* X0   = (const float*)d_in[12];
    float* out = (float*)d_out;

    cudaFuncSetAttribute(k_fp, cudaFuncAttributeMaxDynamicSharedMemorySize, FP_SMEM);

    k_init<<<(Nn * Hh + 255) / 256, 256>>>(X0);
    k_prep<<<(INF_ * Hh + 255) / 256, 256>>>(Wenc, O1);
    k_proj<<<32, 128>>>(W);
    k_cnt<<<((Nn / 4) * CH) / 256, 256>>>(adj);
    k_off<<<Nn / 256, 256>>>();
    k_fill<<<((Nn / 4) * CH) / 256, 256>>>(adj);
    k_enc<<<Nn / 8, 128>>>(x, benc, lng, lnb);
    k_fp<<<NBLK, 512, FP_SMEM>>>();
    k_epi<<<Nn, 128>>>(Wv, bv, lng, lnb, out);
}